// round 1
// baseline (speedup 1.0000x reference)
#include <cuda_runtime.h>
#include <math.h>

#define BATCH 8
#define NC 80
#define NA 8400
#define NA0 6400
#define NA1 1600
#define NA2 400
#define PRE_TOPK 5000
#define KMAX 100
#define TOTK (NC*KMAX)   /* 8000 kept entries per image */
#define SCORE_THR 0.01f
#define IOU_THR 0.65f

// ---------------- scratch (no allocation allowed) ----------------
__device__ float g_scores[BATCH*NC*NA];        // [b][c][a]
__device__ float g_boxes [BATCH*NA*4];         // [b][a][4] xyxy
__device__ float g_kept_score[BATCH*NC*KMAX];  // per-class NMS outputs
__device__ float g_kept_box  [BATCH*NC*KMAX*4];

__device__ __forceinline__ float sigmoidf(float x){ return 1.0f/(1.0f+expf(-x)); }

// ---------------- kernel 1: scores = sigmoid(cls)*sigmoid(obj) ----------------
__global__ void k_scores(const float* __restrict__ cls0, const float* __restrict__ obj0,
                         const float* __restrict__ cls1, const float* __restrict__ obj1,
                         const float* __restrict__ cls2, const float* __restrict__ obj2){
    int idx = blockIdx.x*blockDim.x + threadIdx.x;
    if (idx >= BATCH*NC*NA) return;
    int a = idx % NA;
    int t = idx / NA;
    int c = t % NC;
    int b = t / NC;
    float cv, ov;
    if (a < NA0){
        cv = cls0[((size_t)b*NC + c)*NA0 + a];
        ov = obj0[(size_t)b*NA0 + a];
    } else if (a < NA0+NA1){
        int hw = a - NA0;
        cv = cls1[((size_t)b*NC + c)*NA1 + hw];
        ov = obj1[(size_t)b*NA1 + hw];
    } else {
        int hw = a - NA0 - NA1;
        cv = cls2[((size_t)b*NC + c)*NA2 + hw];
        ov = obj2[(size_t)b*NA2 + hw];
    }
    g_scores[idx] = sigmoidf(cv)*sigmoidf(ov);
}

// ---------------- kernel 2: decode boxes (per (b,anchor)) ----------------
__global__ void k_decode(const float* __restrict__ bb0, const float* __restrict__ bb1,
                         const float* __restrict__ bb2){
    int idx = blockIdx.x*blockDim.x + threadIdx.x;
    if (idx >= BATCH*NA) return;
    int a = idx % NA, b = idx / NA;
    float p0,p1,p2,p3, px,py,st;
    if (a < NA0){
        int hw = a; const float* p = bb0 + (size_t)b*4*NA0;
        p0=p[hw]; p1=p[NA0+hw]; p2=p[2*NA0+hw]; p3=p[3*NA0+hw];
        px = (float)(hw % 80) * 8.f; py = (float)(hw / 80) * 8.f; st = 8.f;
    } else if (a < NA0+NA1){
        int hw = a - NA0; const float* p = bb1 + (size_t)b*4*NA1;
        p0=p[hw]; p1=p[NA1+hw]; p2=p[2*NA1+hw]; p3=p[3*NA1+hw];
        px = (float)(hw % 40) * 16.f; py = (float)(hw / 40) * 16.f; st = 16.f;
    } else {
        int hw = a - NA0 - NA1; const float* p = bb2 + (size_t)b*4*NA2;
        p0=p[hw]; p1=p[NA2+hw]; p2=p[2*NA2+hw]; p3=p[3*NA2+hw];
        px = (float)(hw % 20) * 32.f; py = (float)(hw / 20) * 32.f; st = 32.f;
    }
    float cx = p0*st + px;
    float cy = p1*st + py;
    float w  = expf(p2)*st;
    float h  = expf(p3)*st;
    float* o = &g_boxes[(size_t)idx*4];
    o[0] = cx - w*0.5f;
    o[1] = cy - h*0.5f;
    o[2] = cx + w*0.5f;
    o[3] = cy + h*0.5f;
}

// ---------------- kernel 3: per-(b,c) top-5000 threshold + greedy NMS ----------------
__global__ __launch_bounds__(256) void k_nms(){
    extern __shared__ float sm[];
    float* sc  = sm;                 // NA score column
    float* cx1 = sm + NA;            // PRE_TOPK each (SoA candidates)
    float* cy1 = cx1 + PRE_TOPK;
    float* cx2 = cy1 + PRE_TOPK;
    float* cy2 = cx2 + PRE_TOPK;
    float* cs  = cy2 + PRE_TOPK;
    __shared__ unsigned hist[256];
    __shared__ float wv[8]; __shared__ int wi[8];
    __shared__ unsigned s_prefix; __shared__ int s_k; __shared__ int s_cnt;

    int tid = threadIdx.x;
    int bc  = blockIdx.x;            // b*NC + c
    int b   = bc / NC;

    const float* gsc = g_scores + (size_t)bc*NA;
    for (int a = tid; a < NA; a += 256) sc[a] = gsc[a];
    if (tid == 0){ s_prefix = 0u; s_k = PRE_TOPK; s_cnt = 0; }
    __syncthreads();

    // radix select: exact value of the 5000th-largest score (positive floats -> uint order)
    for (int shift = 24; shift >= 0; shift -= 8){
        hist[tid] = 0;
        __syncthreads();
        unsigned pre  = s_prefix;
        unsigned mask = (shift == 24) ? 0u : (0xFFFFFFFFu << (shift+8));
        for (int a = tid; a < NA; a += 256){
            unsigned v = __float_as_uint(sc[a]);
            if ((v & mask) == pre) atomicAdd(&hist[(v>>shift)&255], 1u);
        }
        __syncthreads();
        if (tid == 0){
            int k = s_k;
            int bin = 255; unsigned cum = hist[255];
            while ((int)cum < k && bin > 0){ bin--; cum += hist[bin]; }
            s_k = k - (int)(cum - hist[bin]);
            s_prefix = pre | ((unsigned)bin << shift);
        }
        __syncthreads();
    }
    float T = __uint_as_float(s_prefix);

    // compact active candidates (score >= T AND score > 0.01) into SMEM SoA
    for (int a = tid; a < NA; a += 256){
        float s = sc[a];
        if (s > SCORE_THR && s >= T){
            int p = atomicAdd(&s_cnt, 1);
            if (p < PRE_TOPK){
                const float4 bb = *reinterpret_cast<const float4*>(&g_boxes[((size_t)b*NA + a)*4]);
                cx1[p]=bb.x; cy1[p]=bb.y; cx2[p]=bb.z; cy2[p]=bb.w; cs[p]=s;
            }
        }
    }
    __syncthreads();
    int M = min(s_cnt, PRE_TOPK);

    float* keptS = g_kept_score + (size_t)bc*KMAX;
    float* keptB = g_kept_box   + (size_t)bc*KMAX*4;

    int it;
    for (it = 0; it < KMAX; it++){
        // block argmax over candidate scores
        float bv = -2.f; int bi = -1;
        for (int i = tid; i < M; i += 256){ float s = cs[i]; if (s > bv){ bv = s; bi = i; } }
        for (int off = 16; off; off >>= 1){
            float ov = __shfl_down_sync(0xFFFFFFFFu, bv, off);
            int   oi = __shfl_down_sync(0xFFFFFFFFu, bi, off);
            if (ov > bv){ bv = ov; bi = oi; }
        }
        if ((tid & 31) == 0){ wv[tid>>5] = bv; wi[tid>>5] = bi; }
        __syncthreads();
        if (tid == 0){
            for (int w = 1; w < 8; w++) if (wv[w] > wv[0]){ wv[0]=wv[w]; wi[0]=wi[w]; }
        }
        __syncthreads();
        bv = wv[0]; bi = wi[0];
        if (bv <= 0.f) break;

        float bx1 = cx1[bi], by1 = cy1[bi], bx2 = cx2[bi], by2 = cy2[bi];
        if (tid == 0){
            keptS[it] = bv;
            keptB[it*4+0]=bx1; keptB[it*4+1]=by1; keptB[it*4+2]=bx2; keptB[it*4+3]=by2;
        }
        float ba = (bx2-bx1)*(by2-by1);
        for (int i = tid; i < M; i += 256){
            float s = cs[i];
            if (s < 0.f) continue;                    // already suppressed
            float x1=cx1[i], y1=cy1[i], x2=cx2[i], y2=cy2[i];
            float tlx = fmaxf(bx1, x1), tly = fmaxf(by1, y1);
            float brx = fminf(bx2, x2), bry = fminf(by2, y2);
            float ww = fmaxf(brx - tlx, 0.f), hh = fmaxf(bry - tly, 0.f);
            float inter = ww*hh;
            float a2 = (x2-x1)*(y2-y1);
            float iou = __fdiv_rn(inter, ba + a2 - inter + 1e-6f);  // IEEE div, matches ref
            if (iou > IOU_THR || i == bi) cs[i] = -1.f;
        }
        __syncthreads();
    }
    // fill unused kept slots deterministically
    for (int j = tid; j < KMAX; j += 256){
        if (j >= it){
            keptS[j] = -1.f;
            keptB[j*4+0]=0.f; keptB[j*4+1]=0.f; keptB[j*4+2]=0.f; keptB[j*4+3]=0.f;
        }
    }
}

// ---------------- kernel 4: per-image global top-100 (sorted, stable ties) ----------------
__global__ __launch_bounds__(256) void k_final(float* __restrict__ out){
    __shared__ float fsc[TOTK];
    __shared__ unsigned long long wk[8];
    __shared__ int s_bi;
    int tid = threadIdx.x, b = blockIdx.x;
    const float* ks = g_kept_score + (size_t)b*TOTK;
    for (int j = tid; j < TOTK; j += 256) fsc[j] = ks[j];
    __syncthreads();

    float* out_num = out;
    float* out_box = out + BATCH;
    float* out_sc  = out + BATCH + (size_t)BATCH*KMAX*4;
    float* out_cl  = out + BATCH + (size_t)BATCH*KMAX*4 + (size_t)BATCH*KMAX;

    int nvalid = 0;
    for (int k = 0; k < KMAX; k++){
        unsigned long long best = 0ull;
        for (int j = tid; j < TOTK; j += 256){
            unsigned u = __float_as_uint(fsc[j]);
            u = (u & 0x80000000u) ? ~u : (u | 0x80000000u);   // order-preserving map
            unsigned long long key = ((unsigned long long)u << 32) | (unsigned long long)(0xFFFFFFFFu - (unsigned)j);
            if (key > best) best = key;                        // ties -> lower index
        }
        for (int off = 16; off; off >>= 1){
            unsigned long long o = __shfl_down_sync(0xFFFFFFFFu, best, off);
            if (o > best) best = o;
        }
        if ((tid & 31) == 0) wk[tid>>5] = best;
        __syncthreads();
        if (tid == 0){
            for (int w = 1; w < 8; w++) if (wk[w] > wk[0]) wk[0] = wk[w];
            s_bi = (int)(0xFFFFFFFFu - (unsigned)(wk[0] & 0xFFFFFFFFull));
        }
        __syncthreads();
        int bi = s_bi;
        if (tid == 0){
            float bv = fsc[bi];
            bool valid = bv > 0.f;
            if (valid) nvalid++;
            out_sc[(size_t)b*KMAX + k] = valid ? bv : 0.f;
            out_cl[(size_t)b*KMAX + k] = valid ? (float)(bi / KMAX) : -1.f;
            const float* bb = &g_kept_box[((size_t)b*TOTK + bi)*4];
            float* ob = &out_box[((size_t)b*KMAX + k)*4];
            ob[0] = valid ? bb[0] : 0.f;
            ob[1] = valid ? bb[1] : 0.f;
            ob[2] = valid ? bb[2] : 0.f;
            ob[3] = valid ? bb[3] : 0.f;
            fsc[bi] = -3.0f;   // remove from further selection
        }
        __syncthreads();
    }
    if (tid == 0) out_num[b] = (float)nvalid;
}

// ---------------- launch ----------------
extern "C" void kernel_launch(void* const* d_in, const int* in_sizes, int n_in,
                              void* d_out, int out_size){
    const float* cls0 = (const float*)d_in[0];
    const float* bb0  = (const float*)d_in[1];
    const float* obj0 = (const float*)d_in[2];
    const float* cls1 = (const float*)d_in[3];
    const float* bb1  = (const float*)d_in[4];
    const float* obj1 = (const float*)d_in[5];
    const float* cls2 = (const float*)d_in[6];
    const float* bb2  = (const float*)d_in[7];
    const float* obj2 = (const float*)d_in[8];
    float* out = (float*)d_out;

    int n1 = BATCH*NC*NA;
    k_scores<<<(n1+255)/256, 256>>>(cls0, obj0, cls1, obj1, cls2, obj2);
    int n2 = BATCH*NA;
    k_decode<<<(n2+255)/256, 256>>>(bb0, bb1, bb2);

    size_t smem = (size_t)(NA + 5*PRE_TOPK)*sizeof(float);   // 133,600 B
    cudaFuncSetAttribute(k_nms, cudaFuncAttributeMaxDynamicSharedMemorySize, (int)smem);
    k_nms<<<BATCH*NC, 256, smem>>>();

    k_final<<<BATCH, 256>>>(out);
}

// round 2
// speedup vs baseline: 13.7582x; 13.7582x over previous
#include <cuda_runtime.h>
#include <math.h>

#define BATCH 8
#define NC 80
#define NA 8400
#define NA0 6400
#define NA1 1600
#define NA2 400
#define PRE_TOPK 5000
#define KMAX 100
#define TOTK (NC*KMAX)
#define SCORE_THR 0.01f
#define IOU_THR 0.65f
#define NTH 256
#define CAP 512      /* batch capacity (sorted) */
#define BSEL 256     /* batch selection size    */
#define FSORT 256    /* final sort size         */

// ---------------- scratch ----------------
__device__ float g_boxes[BATCH*NA*4];          // [b][a][4] xyxy
__device__ float g_kept_score[BATCH*TOTK];     // per-class NMS outputs
__device__ float g_kept_box  [BATCH*TOTK*4];

__device__ __forceinline__ float sigmoidf(float x){ return 1.0f/(1.0f+expf(-x)); }

// ---------------- kernel 1: decode boxes ----------------
__global__ void k_decode(const float* __restrict__ bb0, const float* __restrict__ bb1,
                         const float* __restrict__ bb2){
    int idx = blockIdx.x*blockDim.x + threadIdx.x;
    if (idx >= BATCH*NA) return;
    int a = idx % NA, b = idx / NA;
    float p0,p1,p2,p3, px,py,st;
    if (a < NA0){
        int hw = a; const float* p = bb0 + (size_t)b*4*NA0;
        p0=p[hw]; p1=p[NA0+hw]; p2=p[2*NA0+hw]; p3=p[3*NA0+hw];
        px = (float)(hw % 80) * 8.f;  py = (float)(hw / 80) * 8.f;  st = 8.f;
    } else if (a < NA0+NA1){
        int hw = a - NA0; const float* p = bb1 + (size_t)b*4*NA1;
        p0=p[hw]; p1=p[NA1+hw]; p2=p[2*NA1+hw]; p3=p[3*NA1+hw];
        px = (float)(hw % 40) * 16.f; py = (float)(hw / 40) * 16.f; st = 16.f;
    } else {
        int hw = a - NA0 - NA1; const float* p = bb2 + (size_t)b*4*NA2;
        p0=p[hw]; p1=p[NA2+hw]; p2=p[2*NA2+hw]; p3=p[3*NA2+hw];
        px = (float)(hw % 20) * 32.f; py = (float)(hw / 20) * 32.f; st = 32.f;
    }
    float cx = p0*st + px, cy = p1*st + py;
    float w = expf(p2)*st,  h = expf(p3)*st;
    float* o = &g_boxes[(size_t)idx*4];
    o[0] = cx - w*0.5f; o[1] = cy - h*0.5f; o[2] = cx + w*0.5f; o[3] = cy + h*0.5f;
}

// ---------------- kernel 2: fused scores + batched-sorted greedy NMS ----------------
__global__ __launch_bounds__(NTH) void k_nms(
    const float* __restrict__ cls0, const float* __restrict__ obj0,
    const float* __restrict__ cls1, const float* __restrict__ obj1,
    const float* __restrict__ cls2, const float* __restrict__ obj2){

    extern __shared__ char smraw[];
    unsigned* sc = (unsigned*)smraw;                         // NA score bits
    unsigned long long* key = (unsigned long long*)(smraw + (size_t)NA*4);
    float* bx1 = (float*)(smraw + (size_t)NA*4 + (size_t)CAP*8);
    float* by1 = bx1 + CAP;  float* bx2 = by1 + CAP;  float* by2 = bx2 + CAP;
    float* kx1 = by2 + CAP;  float* ky1 = kx1 + KMAX;
    float* kx2 = ky1 + KMAX; float* ky2 = kx2 + KMAX;
    float* ksc = ky2 + KMAX; float* kar = ksc + KMAX;

    __shared__ unsigned hist[256];
    __shared__ unsigned suf[257];
    __shared__ unsigned s_pref; __shared__ int s_kkv;
    __shared__ int s_cnt, s_kept, s_rank;

    int tid = threadIdx.x;
    int bc  = blockIdx.x;         // b*NC + c
    int b = bc / NC, c = bc % NC;

    // fused score computation: sigmoid(cls)*sigmoid(obj) per anchor
    {
        const float* o0 = obj0 + (size_t)b*NA0;
        const float* c0 = cls0 + ((size_t)b*NC + c)*NA0;
        for (int a = tid; a < NA0; a += NTH)
            sc[a] = __float_as_uint(sigmoidf(c0[a])*sigmoidf(o0[a]));
        const float* o1 = obj1 + (size_t)b*NA1;
        const float* c1 = cls1 + ((size_t)b*NC + c)*NA1;
        for (int a = tid; a < NA1; a += NTH)
            sc[NA0+a] = __float_as_uint(sigmoidf(c1[a])*sigmoidf(o1[a]));
        const float* o2 = obj2 + (size_t)b*NA2;
        const float* c2 = cls2 + ((size_t)b*NC + c)*NA2;
        for (int a = tid; a < NA2; a += NTH)
            sc[NA0+NA1+a] = __float_as_uint(sigmoidf(c2[a])*sigmoidf(o2[a]));
    }
    if (tid == 0){ s_kept = 0; s_rank = 0; }
    __syncthreads();

    const unsigned LO = __float_as_uint(SCORE_THR);  // s > 0.01  <=>  bits > LO (positive floats)
    unsigned HI = 0xFFFFFFFFu;                       // strict upper bound on bits

    while (true){
        // ---- count candidates in (LO, HI) ----
        hist[tid] = 0; __syncthreads();
        for (int a = tid; a < NA; a += NTH){
            unsigned v = sc[a];
            if (v > LO && v < HI) atomicAdd(&hist[v>>24], 1u);
        }
        __syncthreads();
        suf[tid] = hist[tid]; if (tid == 0) suf[256] = 0;
        __syncthreads();
        for (int st = 1; st < 256; st <<= 1){
            unsigned add = (tid + st < 256) ? suf[tid+st] : 0u;
            __syncthreads();
            suf[tid] += add;
            __syncthreads();
        }
        int total = (int)suf[0];
        __syncthreads();
        if (total == 0) break;

        unsigned T;
        if (total <= CAP){
            T = LO + 1;  // take all remaining
        } else {
            // radix select: exact bits of BSEL-th largest in (LO,HI)
            unsigned prefix = 0; int kk = BSEL;
            for (int shift = 24; shift >= 0; shift -= 8){
                hist[tid] = 0; __syncthreads();
                unsigned mask = (shift == 24) ? 0u : (0xFFFFFFFFu << (shift+8));
                for (int a = tid; a < NA; a += NTH){
                    unsigned v = sc[a];
                    if (v > LO && v < HI && (v & mask) == prefix)
                        atomicAdd(&hist[(v>>shift)&255], 1u);
                }
                __syncthreads();
                suf[tid] = hist[tid]; if (tid == 0) suf[256] = 0;
                __syncthreads();
                for (int st = 1; st < 256; st <<= 1){
                    unsigned add = (tid + st < 256) ? suf[tid+st] : 0u;
                    __syncthreads();
                    suf[tid] += add;
                    __syncthreads();
                }
                if (suf[tid] >= (unsigned)kk && suf[tid+1] < (unsigned)kk){
                    s_pref = prefix | ((unsigned)tid << shift);
                    s_kkv  = kk - (int)suf[tid+1];
                }
                __syncthreads();
                prefix = s_pref; kk = s_kkv;
                __syncthreads();
            }
            T = prefix;
        }

        // ---- compact candidates with bits in [T, HI) into keys ----
        if (tid == 0) s_cnt = 0;
        __syncthreads();
        for (int a = tid; a < NA; a += NTH){
            unsigned v = sc[a];
            if (v >= T && v < HI && v > LO){
                int p = atomicAdd(&s_cnt, 1);
                if (p < CAP)
                    key[p] = ((unsigned long long)v << 32) | (unsigned)(NA-1-a);
            }
        }
        __syncthreads();
        int cnt = min(s_cnt, CAP);
        for (int p = cnt + tid; p < CAP; p += NTH) key[p] = 0ull;
        __syncthreads();

        // ---- bitonic sort ascending (desc = read from top) ----
        for (int ksz = 2; ksz <= CAP; ksz <<= 1){
            for (int j = ksz >> 1; j > 0; j >>= 1){
                for (int idx = tid; idx < CAP; idx += NTH){
                    int l = idx ^ j;
                    if (l > idx){
                        unsigned long long a0 = key[idx], a1 = key[l];
                        bool up = ((idx & ksz) == 0);
                        if ((a0 > a1) == up){ key[idx] = a1; key[l] = a0; }
                    }
                }
                __syncthreads();
            }
        }

        // ---- stage boxes of sorted candidates (desc order t) ----
        for (int t = tid; t < cnt; t += NTH){
            unsigned long long k2 = key[CAP-1-t];
            int a = NA - 1 - (int)(k2 & 0xFFFFFFFFull);
            const float4 bb = *reinterpret_cast<const float4*>(&g_boxes[((size_t)b*NA + a)*4]);
            bx1[t] = bb.x; by1[t] = bb.y; bx2[t] = bb.z; by2[t] = bb.w;
        }
        __syncthreads();

        // ---- warp-0 serial greedy scan in descending score order ----
        if (tid < 32){
            int kept = s_kept, rank = s_rank;
            for (int t = 0; t < cnt && kept < KMAX && rank < PRE_TOPK; t++){
                rank++;
                float x1 = bx1[t], y1 = by1[t], x2 = bx2[t], y2 = by2[t];
                float a2 = (x2 - x1)*(y2 - y1);
                bool sup = false;
                for (int m = tid; m < kept; m += 32){
                    float tlx = fmaxf(kx1[m], x1), tly = fmaxf(ky1[m], y1);
                    float brx = fminf(kx2[m], x2), bry = fminf(ky2[m], y2);
                    float ww = fmaxf(brx - tlx, 0.f), hh = fmaxf(bry - tly, 0.f);
                    float inter = ww*hh;
                    float iou = __fdiv_rn(inter, kar[m] + a2 - inter + 1e-6f);
                    sup |= (iou > IOU_THR);
                }
                if (!__ballot_sync(0xFFFFFFFFu, sup)){
                    if (tid == 0){
                        kx1[kept]=x1; ky1[kept]=y1; kx2[kept]=x2; ky2[kept]=y2;
                        kar[kept]=a2;
                        ksc[kept]=__uint_as_float((unsigned)(key[CAP-1-t] >> 32));
                    }
                    kept++;
                }
            }
            if (tid == 0){ s_kept = kept; s_rank = rank; }
        }
        __syncthreads();
        if (s_kept >= KMAX || s_rank >= PRE_TOPK) break;
        HI = T;     // next batch: strictly below this batch's threshold
        __syncthreads();
    }

    // ---- write per-class kept outputs ----
    int kept = s_kept;
    float* keptS = g_kept_score + (size_t)bc*KMAX;
    float* keptB = g_kept_box   + (size_t)bc*KMAX*4;
    for (int j = tid; j < KMAX; j += NTH){
        if (j < kept){
            keptS[j] = ksc[j];
            keptB[j*4+0]=kx1[j]; keptB[j*4+1]=ky1[j];
            keptB[j*4+2]=kx2[j]; keptB[j*4+3]=ky2[j];
        } else {
            keptS[j] = -1.f;
            keptB[j*4+0]=0.f; keptB[j*4+1]=0.f; keptB[j*4+2]=0.f; keptB[j*4+3]=0.f;
        }
    }
}

// ---------------- kernel 3: per-image global top-100 ----------------
__global__ __launch_bounds__(NTH) void k_final(float* __restrict__ out){
    __shared__ unsigned mapped[TOTK];
    __shared__ unsigned long long key[FSORT];
    __shared__ unsigned hist[256];
    __shared__ unsigned suf[257];
    __shared__ unsigned s_pref; __shared__ int s_kkv;
    __shared__ int s_cnt;

    int tid = threadIdx.x, b = blockIdx.x;
    const float* ks = g_kept_score + (size_t)b*TOTK;
    for (int j = tid; j < TOTK; j += NTH){
        unsigned u = __float_as_uint(ks[j]);
        mapped[j] = (u & 0x80000000u) ? ~u : (u | 0x80000000u);   // order-preserving
    }
    __syncthreads();

    // radix select: 100th-largest mapped value
    unsigned prefix = 0; int kk = KMAX;
    for (int shift = 24; shift >= 0; shift -= 8){
        hist[tid] = 0; __syncthreads();
        unsigned mask = (shift == 24) ? 0u : (0xFFFFFFFFu << (shift+8));
        for (int j = tid; j < TOTK; j += NTH){
            unsigned v = mapped[j];
            if ((v & mask) == prefix) atomicAdd(&hist[(v>>shift)&255], 1u);
        }
        __syncthreads();
        suf[tid] = hist[tid]; if (tid == 0) suf[256] = 0;
        __syncthreads();
        for (int st = 1; st < 256; st <<= 1){
            unsigned add = (tid + st < 256) ? suf[tid+st] : 0u;
            __syncthreads();
            suf[tid] += add;
            __syncthreads();
        }
        if (suf[tid] >= (unsigned)kk && suf[tid+1] < (unsigned)kk){
            s_pref = prefix | ((unsigned)tid << shift);
            s_kkv  = kk - (int)suf[tid+1];
        }
        __syncthreads();
        prefix = s_pref; kk = s_kkv;
        __syncthreads();
    }
    unsigned T = prefix;
    const unsigned MAP0 = 0x80000000u;   // mapped(0.0f); valid <=> mapped > MAP0

    if (tid == 0) s_cnt = 0;
    __syncthreads();
    for (int j = tid; j < TOTK; j += NTH){
        unsigned v = mapped[j];
        if (v >= T && v > MAP0){
            int p = atomicAdd(&s_cnt, 1);
            if (p < FSORT)
                key[p] = ((unsigned long long)v << 32) | (0xFFFFFFFFu - (unsigned)j);
        }
    }
    __syncthreads();
    int cnt = min(s_cnt, FSORT);
    for (int p = cnt + tid; p < FSORT; p += NTH) key[p] = 0ull;
    __syncthreads();

    for (int ksz = 2; ksz <= FSORT; ksz <<= 1){
        for (int j = ksz >> 1; j > 0; j >>= 1){
            if (tid < FSORT){
                int idx = tid, l = idx ^ j;
                if (l > idx){
                    unsigned long long a0 = key[idx], a1 = key[l];
                    bool up = ((idx & ksz) == 0);
                    if ((a0 > a1) == up){ key[idx] = a1; key[l] = a0; }
                }
            }
            __syncthreads();
        }
    }

    float* out_num = out;
    float* out_box = out + BATCH;
    float* out_sc  = out + BATCH + (size_t)BATCH*KMAX*4;
    float* out_cl  = out + BATCH + (size_t)BATCH*KMAX*4 + (size_t)BATCH*KMAX;

    for (int k = tid; k < KMAX; k += NTH){
        bool valid = (k < cnt);
        float s = 0.f, cl = -1.f, b0=0.f, b1=0.f, b2=0.f, b3=0.f;
        if (valid){
            unsigned long long k2 = key[FSORT-1-k];
            int flat = (int)(0xFFFFFFFFu - (unsigned)(k2 & 0xFFFFFFFFull));
            s  = g_kept_score[(size_t)b*TOTK + flat];
            cl = (float)(flat / KMAX);
            const float* bb = &g_kept_box[((size_t)b*TOTK + flat)*4];
            b0 = bb[0]; b1 = bb[1]; b2 = bb[2]; b3 = bb[3];
        }
        out_sc[(size_t)b*KMAX + k] = s;
        out_cl[(size_t)b*KMAX + k] = cl;
        float* ob = &out_box[((size_t)b*KMAX + k)*4];
        ob[0]=b0; ob[1]=b1; ob[2]=b2; ob[3]=b3;
    }
    if (tid == 0) out_num[b] = (float)min(cnt, KMAX);
}

// ---------------- launch ----------------
extern "C" void kernel_launch(void* const* d_in, const int* in_sizes, int n_in,
                              void* d_out, int out_size){
    const float* cls0 = (const float*)d_in[0];
    const float* bb0  = (const float*)d_in[1];
    const float* obj0 = (const float*)d_in[2];
    const float* cls1 = (const float*)d_in[3];
    const float* bb1  = (const float*)d_in[4];
    const float* obj1 = (const float*)d_in[5];
    const float* cls2 = (const float*)d_in[6];
    const float* bb2  = (const float*)d_in[7];
    const float* obj2 = (const float*)d_in[8];
    float* out = (float*)d_out;

    int n2 = BATCH*NA;
    k_decode<<<(n2+255)/256, 256>>>(bb0, bb1, bb2);

    size_t smem = (size_t)NA*4 + (size_t)CAP*8 + (size_t)CAP*4*4 + (size_t)KMAX*6*4;
    static int smem_set = 0;
    if (!smem_set){
        cudaFuncSetAttribute(k_nms, cudaFuncAttributeMaxDynamicSharedMemorySize, (int)smem);
        smem_set = 1;
    }
    k_nms<<<BATCH*NC, NTH, smem>>>(cls0, obj0, cls1, obj1, cls2, obj2);

    k_final<<<BATCH, NTH>>>(out);
}

// round 3
// speedup vs baseline: 39.5711x; 2.8762x over previous
#include <cuda_runtime.h>
#include <math.h>

#define BATCH 8
#define NC 80
#define NA 8400
#define NA0 6400
#define NA1 1600
#define NA2 400
#define PRE_TOPK 5000
#define KMAX 100
#define TOTK (NC*KMAX)
#define SCORE_THR 0.01f
#define IOU_THR 0.65f
#define NTH 256
#define CAP 512
#define BSEL 256
#define FSORT 256
#define PADKEY 0xFFFFFFFFFFFFFFFFull
#define FULLM 0xFFFFFFFFu

// ---------------- scratch ----------------
__device__ float g_boxes[BATCH*NA*4];        // [b][a][4] xyxy
__device__ float g_qobj [BATCH*NA];          // 1 + exp(-obj)
__device__ float g_sobj [BATCH*NA];          // exact sigmoid(obj) = 1/(1+exp(-obj))
__device__ float g_kept_score[BATCH*TOTK];
__device__ float g_kept_box  [BATCH*TOTK*4];

// decision-exact IoU>thr test; division only in a tiny ambiguity band
__device__ __forceinline__ bool iou_sup(float SX1,float SY1,float SX2,float SY2,float SAR,
                                        float x1,float y1,float x2,float y2,float ar){
    float tlx = fmaxf(SX1, x1), tly = fmaxf(SY1, y1);
    float brx = fminf(SX2, x2), bry = fminf(SY2, y2);
    float ww = fmaxf(brx - tlx, 0.f), hh = fmaxf(bry - tly, 0.f);
    float inter = ww*hh;
    float denom = SAR + ar - inter + 1e-6f;
    float d = inter - IOU_THR*denom;
    if (fabsf(d) > 1e-4f*denom) return d > 0.f;
    return __fdiv_rn(inter, denom) > IOU_THR;   // exact path for near-boundary
}

// ---------------- kernel 1: decode boxes + objectness precompute ----------------
__global__ void k_decode(const float* __restrict__ bb0, const float* __restrict__ bb1,
                         const float* __restrict__ bb2,
                         const float* __restrict__ obj0, const float* __restrict__ obj1,
                         const float* __restrict__ obj2){
    int idx = blockIdx.x*blockDim.x + threadIdx.x;
    if (idx >= BATCH*NA) return;
    int a = idx % NA, b = idx / NA;
    float p0,p1,p2,p3, px,py,st, ov;
    if (a < NA0){
        int hw = a; const float* p = bb0 + (size_t)b*4*NA0;
        p0=p[hw]; p1=p[NA0+hw]; p2=p[2*NA0+hw]; p3=p[3*NA0+hw];
        ov = obj0[(size_t)b*NA0 + hw];
        px = (float)(hw % 80) * 8.f;  py = (float)(hw / 80) * 8.f;  st = 8.f;
    } else if (a < NA0+NA1){
        int hw = a - NA0; const float* p = bb1 + (size_t)b*4*NA1;
        p0=p[hw]; p1=p[NA1+hw]; p2=p[2*NA1+hw]; p3=p[3*NA1+hw];
        ov = obj1[(size_t)b*NA1 + hw];
        px = (float)(hw % 40) * 16.f; py = (float)(hw / 40) * 16.f; st = 16.f;
    } else {
        int hw = a - NA0 - NA1; const float* p = bb2 + (size_t)b*4*NA2;
        p0=p[hw]; p1=p[NA2+hw]; p2=p[2*NA2+hw]; p3=p[3*NA2+hw];
        ov = obj2[(size_t)b*NA2 + hw];
        px = (float)(hw % 20) * 32.f; py = (float)(hw / 20) * 32.f; st = 32.f;
    }
    float cx = p0*st + px, cy = p1*st + py;
    float w = expf(p2)*st,  h = expf(p3)*st;
    float* o = &g_boxes[(size_t)idx*4];
    o[0] = cx - w*0.5f; o[1] = cy - h*0.5f; o[2] = cx + w*0.5f; o[3] = cy + h*0.5f;
    float qo = 1.0f + expf(-ov);
    g_qobj[idx] = qo;
    g_sobj[idx] = 1.0f/(1.0f+expf(-ov));   // bit-identical to reference sigmoid path
}

// ---------------- kernel 2: selection + NMS ----------------
__global__ __launch_bounds__(NTH, 5) void k_nms(
    const float* __restrict__ cls0, const float* __restrict__ cls1,
    const float* __restrict__ cls2){

    extern __shared__ char smraw[];
    unsigned* sc = (unsigned*)smraw;                                      // NA q-bits
    unsigned long long* key = (unsigned long long*)(smraw + (size_t)NA*4);// CAP keys

    __shared__ float kx1[KMAX], ky1[KMAX], kx2[KMAX], ky2[KMAX], ksc[KMAX], kar[KMAX];
    __shared__ unsigned hist[256];
    __shared__ int supv[32];
    __shared__ unsigned s_pref; __shared__ int s_kkv; __shared__ int s_total;
    __shared__ int s_cnt, s_kept, s_rank;

    int tid = threadIdx.x;
    int lane = tid & 31, w = tid >> 5;
    int bc  = blockIdx.x;
    int b = bc / NC, c = bc % NC;

    const float* sobj = g_sobj + (size_t)b*NA;
    const float* c0 = cls0 + ((size_t)b*NC + c)*NA0;
    const float* c1 = cls1 + ((size_t)b*NC + c)*NA1;
    const float* c2 = cls2 + ((size_t)b*NC + c)*NA2;

    // ---- bulk: q = (1+exp(-cls)) * qobj  (score = 1/q, ascending q = descending score)
    {
        const float4* c0v = (const float4*)c0;
        const float4* c1v = (const float4*)c1;
        const float4* c2v = (const float4*)c2;
        const float4* q0v = (const float4*)(g_qobj + (size_t)b*NA);
        const float4* q1v = (const float4*)(g_qobj + (size_t)b*NA + NA0);
        const float4* q2v = (const float4*)(g_qobj + (size_t)b*NA + NA0 + NA1);
        uint4* scv = (uint4*)sc;
        for (int i = tid; i < NA0/4; i += NTH){
            float4 cv = c0v[i]; float4 qv = q0v[i]; uint4 o;
            o.x = __float_as_uint((1.f+expf(-cv.x))*qv.x);
            o.y = __float_as_uint((1.f+expf(-cv.y))*qv.y);
            o.z = __float_as_uint((1.f+expf(-cv.z))*qv.z);
            o.w = __float_as_uint((1.f+expf(-cv.w))*qv.w);
            scv[i] = o;
        }
        for (int i = tid; i < NA1/4; i += NTH){
            float4 cv = c1v[i]; float4 qv = q1v[i]; uint4 o;
            o.x = __float_as_uint((1.f+expf(-cv.x))*qv.x);
            o.y = __float_as_uint((1.f+expf(-cv.y))*qv.y);
            o.z = __float_as_uint((1.f+expf(-cv.z))*qv.z);
            o.w = __float_as_uint((1.f+expf(-cv.w))*qv.w);
            scv[NA0/4 + i] = o;
        }
        for (int i = tid; i < NA2/4; i += NTH){
            float4 cv = c2v[i]; float4 qv = q2v[i]; uint4 o;
            o.x = __float_as_uint((1.f+expf(-cv.x))*qv.x);
            o.y = __float_as_uint((1.f+expf(-cv.y))*qv.y);
            o.z = __float_as_uint((1.f+expf(-cv.z))*qv.z);
            o.w = __float_as_uint((1.f+expf(-cv.w))*qv.w);
            scv[(NA0+NA1)/4 + i] = o;
        }
    }
    if (tid == 0){ s_kept = 0; s_rank = 0; }
    __syncthreads();

    const unsigned QHI = __float_as_uint(100.0f);   // q < 100  <=>  score > 0.01
    unsigned prevT = 0;
    bool done = false;

    while (!done){
        // ---- pass 1 histogram (top byte) + total count
        hist[tid] = 0; __syncthreads();
        for (int a = tid; a < NA; a += NTH){
            unsigned v = sc[a];
            if (v < QHI && v > prevT) atomicAdd(&hist[v>>24], 1u);
        }
        __syncthreads();
        if (tid < 32){
            unsigned cc[8]; unsigned sum = 0;
            #pragma unroll
            for (int j = 0; j < 8; j++){ cc[j] = hist[tid*8+j]; sum += cc[j]; }
            unsigned incl = sum;
            #pragma unroll
            for (int off = 1; off < 32; off <<= 1){
                unsigned n = __shfl_up_sync(FULLM, incl, off);
                if (lane >= off) incl += n;
            }
            unsigned excl = incl - sum;
            unsigned total = __shfl_sync(FULLM, incl, 31);
            if (lane == 0) s_total = (int)total;
            if (total > CAP){
                int kk = BSEL;
                if ((int)excl < kk && kk <= (int)incl){
                    unsigned run = excl;
                    #pragma unroll
                    for (int j = 0; j < 8; j++){
                        if (run + cc[j] >= (unsigned)kk){
                            s_pref = ((unsigned)(tid*8+j)) << 24;
                            s_kkv  = kk - (int)run;
                            break;
                        }
                        run += cc[j];
                    }
                }
            }
        }
        __syncthreads();
        int total = s_total;
        if (total == 0) break;
        bool takeall = (total <= CAP);
        unsigned T = 0xFFFFFFFFu;

        if (!takeall){
            for (int shift = 16; shift >= 0; shift -= 8){
                unsigned prefix = s_pref; int kk = s_kkv;
                unsigned mask = 0xFFFFFFFFu << (shift+8);
                hist[tid] = 0; __syncthreads();
                for (int a = tid; a < NA; a += NTH){
                    unsigned v = sc[a];
                    if (v < QHI && v > prevT && (v & mask) == prefix)
                        atomicAdd(&hist[(v>>shift)&255], 1u);
                }
                __syncthreads();
                if (tid < 32){
                    unsigned cc[8]; unsigned sum = 0;
                    #pragma unroll
                    for (int j = 0; j < 8; j++){ cc[j] = hist[tid*8+j]; sum += cc[j]; }
                    unsigned incl = sum;
                    #pragma unroll
                    for (int off = 1; off < 32; off <<= 1){
                        unsigned n = __shfl_up_sync(FULLM, incl, off);
                        if (lane >= off) incl += n;
                    }
                    unsigned excl = incl - sum;
                    if ((int)excl < kk && kk <= (int)incl){
                        unsigned run = excl;
                        #pragma unroll
                        for (int j = 0; j < 8; j++){
                            if (run + cc[j] >= (unsigned)kk){
                                s_pref = prefix | (((unsigned)(tid*8+j)) << shift);
                                s_kkv  = kk - (int)run;
                                break;
                            }
                            run += cc[j];
                        }
                    }
                }
                __syncthreads();
            }
            T = s_pref;
        }

        // ---- compact indices of this batch's candidates
        if (tid == 0) s_cnt = 0;
        __syncthreads();
        for (int a = tid; a < NA; a += NTH){
            unsigned v = sc[a];
            if (v < QHI && v > prevT && (takeall || v <= T)){
                int p = atomicAdd(&s_cnt, 1);
                if (p < CAP) key[p] = (unsigned long long)(unsigned)a;
            }
        }
        __syncthreads();
        int cnt = min(s_cnt, CAP);

        // ---- recompute EXACT reference score for selected; build sort keys
        for (int p = tid; p < CAP; p += NTH){
            if (p < cnt){
                int a = (int)(unsigned)key[p];
                float cv;
                if (a < NA0) cv = c0[a];
                else if (a < NA0+NA1) cv = c1[a-NA0];
                else cv = c2[a-NA0-NA1];
                float sg = 1.0f/(1.0f+expf(-cv));     // exact sigmoid(cls)
                float s  = sg * sobj[a];              // exact reference score
                if (s > SCORE_THR)
                    key[p] = ((unsigned long long)(~__float_as_uint(s)) << 32) | (unsigned)a;
                else
                    key[p] = PADKEY;
            } else key[p] = PADKEY;
        }
        __syncthreads();

        // ---- bitonic sort ascending: score desc, ties lower index first
        for (int ksz = 2; ksz <= CAP; ksz <<= 1){
            for (int j = ksz >> 1; j > 0; j >>= 1){
                for (int idx = tid; idx < CAP; idx += NTH){
                    int l = idx ^ j;
                    if (l > idx){
                        unsigned long long a0 = key[idx], a1 = key[l];
                        bool up = ((idx & ksz) == 0);
                        if ((a0 > a1) == up){ key[idx] = a1; key[l] = a0; }
                    }
                }
                __syncthreads();
            }
        }

        // ---- greedy NMS: warp-parallel chunks of 32 candidates
        if (tid < 32) supv[tid] = 0;
        __syncthreads();
        int t0 = 0;
        while (t0 < cnt){
            int K = s_kept, rank = s_rank;
            if (K >= KMAX || rank >= PRE_TOPK) break;
            int chunk_n = min(32, min(cnt - t0, PRE_TOPK - rank));

            bool lv = lane < chunk_n;
            unsigned long long kk64 = lv ? key[t0+lane] : PADKEY;
            bool cvalid = lv && (kk64 != PADKEY);
            float x1=0,y1=0,x2=0,y2=0,ar=0,sval=0;
            if (cvalid){
                int a = (int)(unsigned)(kk64 & 0xFFFFFFFFull);
                sval = __uint_as_float(~(unsigned)(kk64>>32));
                const float4 bb = *reinterpret_cast<const float4*>(&g_boxes[((size_t)b*NA + a)*4]);
                x1=bb.x; y1=bb.y; x2=bb.z; y2=bb.w;
                ar = (x2-x1)*(y2-y1);
            }
            // all 8 warps split the kept-box loop
            bool sup = false;
            if (cvalid){
                for (int m = w; m < K; m += 8)
                    sup |= iou_sup(kx1[m],ky1[m],kx2[m],ky2[m],kar[m], x1,y1,x2,y2,ar);
            }
            if (sup) supv[lane] = 1;
            __syncthreads();

            if (w == 0){
                unsigned validmask = __ballot_sync(FULLM, cvalid);
                unsigned conflict = 0;
                for (int j = 0; j < 31; j++){
                    float X1 = __shfl_sync(FULLM, x1, j);
                    float Y1 = __shfl_sync(FULLM, y1, j);
                    float X2 = __shfl_sync(FULLM, x2, j);
                    float Y2 = __shfl_sync(FULLM, y2, j);
                    float AR = __shfl_sync(FULLM, ar, j);
                    if (cvalid && j < lane && ((validmask>>j)&1u)){
                        if (iou_sup(X1,Y1,X2,Y2,AR, x1,y1,x2,y2,ar)) conflict |= 1u<<j;
                    }
                }
                bool base_ok = cvalid && (supv[lane] == 0);
                unsigned aliveMask = 0;
                for (int j = 0; j < 32; j++){
                    bool mine = (lane == j) && base_ok && ((conflict & aliveMask) == 0);
                    unsigned bmask = __ballot_sync(FULLM, mine);
                    aliveMask |= bmask;
                }
                int pos = K + __popc(aliveMask & ((1u<<lane)-1u));
                if (((aliveMask>>lane)&1u) && pos < KMAX){
                    kx1[pos]=x1; ky1[pos]=y1; kx2[pos]=x2; ky2[pos]=y2;
                    kar[pos]=ar; ksc[pos]=sval;
                }
                if (lane == 0){
                    s_kept = min(K + __popc(aliveMask), KMAX);
                    s_rank = rank + chunk_n;
                }
                supv[lane] = 0;
            }
            __syncthreads();
            t0 += 32;
        }
        if (s_kept >= KMAX || s_rank >= PRE_TOPK || takeall) done = true;
        else prevT = T;
        __syncthreads();
    }

    // ---- per-class outputs
    int kept = s_kept;
    float* keptS = g_kept_score + (size_t)bc*KMAX;
    float* keptB = g_kept_box   + (size_t)bc*KMAX*4;
    for (int j = tid; j < KMAX; j += NTH){
        if (j < kept){
            keptS[j] = ksc[j];
            keptB[j*4+0]=kx1[j]; keptB[j*4+1]=ky1[j];
            keptB[j*4+2]=kx2[j]; keptB[j*4+3]=ky2[j];
        } else {
            keptS[j] = -1.f;
            keptB[j*4+0]=0.f; keptB[j*4+1]=0.f; keptB[j*4+2]=0.f; keptB[j*4+3]=0.f;
        }
    }
}

// ---------------- kernel 3: per-image global top-100 ----------------
__global__ __launch_bounds__(NTH) void k_final(float* __restrict__ out){
    __shared__ unsigned mapped[TOTK];
    __shared__ unsigned long long key[FSORT];
    __shared__ unsigned hist[256];
    __shared__ unsigned suf[257];
    __shared__ unsigned s_pref; __shared__ int s_kkv;
    __shared__ int s_cnt;

    int tid = threadIdx.x, b = blockIdx.x;
    const float* ks = g_kept_score + (size_t)b*TOTK;
    for (int j = tid; j < TOTK; j += NTH){
        unsigned u = __float_as_uint(ks[j]);
        mapped[j] = (u & 0x80000000u) ? ~u : (u | 0x80000000u);
    }
    __syncthreads();

    unsigned prefix = 0; int kk = KMAX;
    for (int shift = 24; shift >= 0; shift -= 8){
        hist[tid] = 0; __syncthreads();
        unsigned mask = (shift == 24) ? 0u : (0xFFFFFFFFu << (shift+8));
        for (int j = tid; j < TOTK; j += NTH){
            unsigned v = mapped[j];
            if ((v & mask) == prefix) atomicAdd(&hist[(v>>shift)&255], 1u);
        }
        __syncthreads();
        suf[tid] = hist[tid]; if (tid == 0) suf[256] = 0;
        __syncthreads();
        for (int st = 1; st < 256; st <<= 1){
            unsigned add = (tid + st < 256) ? suf[tid+st] : 0u;
            __syncthreads();
            suf[tid] += add;
            __syncthreads();
        }
        if (suf[tid] >= (unsigned)kk && suf[tid+1] < (unsigned)kk){
            s_pref = prefix | ((unsigned)tid << shift);
            s_kkv  = kk - (int)suf[tid+1];
        }
        __syncthreads();
        prefix = s_pref; kk = s_kkv;
        __syncthreads();
    }
    unsigned T = prefix;
    const unsigned MAP0 = 0x80000000u;

    if (tid == 0) s_cnt = 0;
    __syncthreads();
    for (int j = tid; j < TOTK; j += NTH){
        unsigned v = mapped[j];
        if (v >= T && v > MAP0){
            int p = atomicAdd(&s_cnt, 1);
            if (p < FSORT)
                key[p] = ((unsigned long long)v << 32) | (0xFFFFFFFFu - (unsigned)j);
        }
    }
    __syncthreads();
    int cnt = min(s_cnt, FSORT);
    for (int p = cnt + tid; p < FSORT; p += NTH) key[p] = 0ull;
    __syncthreads();

    for (int ksz = 2; ksz <= FSORT; ksz <<= 1){
        for (int j = ksz >> 1; j > 0; j >>= 1){
            if (tid < FSORT){
                int idx = tid, l = idx ^ j;
                if (l > idx){
                    unsigned long long a0 = key[idx], a1 = key[l];
                    bool up = ((idx & ksz) == 0);
                    if ((a0 > a1) == up){ key[idx] = a1; key[l] = a0; }
                }
            }
            __syncthreads();
        }
    }

    float* out_num = out;
    float* out_box = out + BATCH;
    float* out_sc  = out + BATCH + (size_t)BATCH*KMAX*4;
    float* out_cl  = out + BATCH + (size_t)BATCH*KMAX*4 + (size_t)BATCH*KMAX;

    for (int k = tid; k < KMAX; k += NTH){
        bool valid = (k < cnt);
        float s = 0.f, cl = -1.f, b0=0.f, b1=0.f, b2=0.f, b3=0.f;
        if (valid){
            unsigned long long k2 = key[FSORT-1-k];
            int flat = (int)(0xFFFFFFFFu - (unsigned)(k2 & 0xFFFFFFFFull));
            s  = g_kept_score[(size_t)b*TOTK + flat];
            cl = (float)(flat / KMAX);
            const float* bb = &g_kept_box[((size_t)b*TOTK + flat)*4];
            b0 = bb[0]; b1 = bb[1]; b2 = bb[2]; b3 = bb[3];
        }
        out_sc[(size_t)b*KMAX + k] = s;
        out_cl[(size_t)b*KMAX + k] = cl;
        float* ob = &out_box[((size_t)b*KMAX + k)*4];
        ob[0]=b0; ob[1]=b1; ob[2]=b2; ob[3]=b3;
    }
    if (tid == 0) out_num[b] = (float)min(cnt, KMAX);
}

// ---------------- launch ----------------
extern "C" void kernel_launch(void* const* d_in, const int* in_sizes, int n_in,
                              void* d_out, int out_size){
    const float* cls0 = (const float*)d_in[0];
    const float* bb0  = (const float*)d_in[1];
    const float* obj0 = (const float*)d_in[2];
    const float* cls1 = (const float*)d_in[3];
    const float* bb1  = (const float*)d_in[4];
    const float* obj1 = (const float*)d_in[5];
    const float* cls2 = (const float*)d_in[6];
    const float* bb2  = (const float*)d_in[7];
    const float* obj2 = (const float*)d_in[8];
    float* out = (float*)d_out;

    int n2 = BATCH*NA;
    k_decode<<<(n2+255)/256, 256>>>(bb0, bb1, bb2, obj0, obj1, obj2);

    size_t smem = (size_t)NA*4 + (size_t)CAP*8;   // 37,696 B (< 48KB default)
    k_nms<<<BATCH*NC, NTH, smem>>>(cls0, cls1, cls2);

    k_final<<<BATCH, NTH>>>(out);
}

// round 4
// speedup vs baseline: 39.9639x; 1.0099x over previous
#include <cuda_runtime.h>
#include <math.h>

#define BATCH 8
#define NC 80
#define NA 8400
#define NA0 6400
#define NA1 1600
#define NA2 400
#define PRE_TOPK 5000
#define KMAX 100
#define TOTK (NC*KMAX)
#define SCORE_THR 0.01f
#define IOU_THR 0.65f
#define NTH 256
#define CAP 512
#define BSEL 256
#define FSORT 256
#define PADKEY 0xFFFFFFFFFFFFFFFFull
#define FULLM 0xFFFFFFFFu

// ---------------- scratch ----------------
__device__ float g_boxes[BATCH*NA*4];        // [b][a][4] xyxy
__device__ float g_qobj [BATCH*NA];          // 1 + exp(-obj)  (exact)
__device__ float g_sobj [BATCH*NA];          // exact sigmoid(obj)
__device__ float g_kept_score[BATCH*TOTK];
__device__ float g_kept_box  [BATCH*TOTK*4];

// decision-exact IoU>thr test; division only in a tiny ambiguity band
__device__ __forceinline__ bool iou_sup(float SX1,float SY1,float SX2,float SY2,float SAR,
                                        float x1,float y1,float x2,float y2,float ar){
    float tlx = fmaxf(SX1, x1), tly = fmaxf(SY1, y1);
    float brx = fminf(SX2, x2), bry = fminf(SY2, y2);
    float ww = fmaxf(brx - tlx, 0.f), hh = fmaxf(bry - tly, 0.f);
    float inter = ww*hh;
    float denom = SAR + ar - inter + 1e-6f;
    float d = inter - IOU_THR*denom;
    if (fabsf(d) > 1e-4f*denom) return d > 0.f;
    return __fdiv_rn(inter, denom) > IOU_THR;
}

// monotone cheap approx of 1+e^{-x} (Schraudolph; no MUFU)
__device__ __forceinline__ float qapprox(float x){
    float t = fminf(fmaxf(-x, -80.f), 80.f);
    int bits = (int)(12102203.0f*t + 1064986316.0f);
    return 1.0f + __int_as_float(bits);
}

// ---------------- kernel 1: decode boxes + objectness (4 anchors/thread) ----------------
__global__ void k_decode(const float* __restrict__ bb0, const float* __restrict__ bb1,
                         const float* __restrict__ bb2,
                         const float* __restrict__ obj0, const float* __restrict__ obj1,
                         const float* __restrict__ obj2){
    const int T0 = BATCH*NA0/4, T1 = BATCH*NA1/4, T2 = BATCH*NA2/4;
    int idx = blockIdx.x*blockDim.x + threadIdx.x;
    if (idx >= T0+T1+T2) return;
    int b, hw4, W, NAl, lvlbase; float st; const float *bb, *ob;
    if (idx < T0){
        b = idx/(NA0/4); hw4 = (idx%(NA0/4))*4; W=80; st=8.f;  NAl=NA0; lvlbase=0;
        bb = bb0 + (size_t)b*4*NA0; ob = obj0 + (size_t)b*NA0;
    } else if (idx < T0+T1){
        int t = idx-T0;
        b = t/(NA1/4); hw4 = (t%(NA1/4))*4; W=40; st=16.f; NAl=NA1; lvlbase=NA0;
        bb = bb1 + (size_t)b*4*NA1; ob = obj1 + (size_t)b*NA1;
    } else {
        int t = idx-T0-T1;
        b = t/(NA2/4); hw4 = (t%(NA2/4))*4; W=20; st=32.f; NAl=NA2; lvlbase=NA0+NA1;
        bb = bb2 + (size_t)b*4*NA2; ob = obj2 + (size_t)b*NA2;
    }
    float4 p0 = *reinterpret_cast<const float4*>(bb + hw4);
    float4 p1 = *reinterpret_cast<const float4*>(bb + NAl   + hw4);
    float4 p2 = *reinterpret_cast<const float4*>(bb + 2*NAl + hw4);
    float4 p3 = *reinterpret_cast<const float4*>(bb + 3*NAl + hw4);
    float4 ov = *reinterpret_cast<const float4*>(ob + hw4);
    float c0a[4] = {p0.x,p0.y,p0.z,p0.w};
    float c1a[4] = {p1.x,p1.y,p1.z,p1.w};
    float c2a[4] = {p2.x,p2.y,p2.z,p2.w};
    float c3a[4] = {p3.x,p3.y,p3.z,p3.w};
    float ova[4] = {ov.x,ov.y,ov.z,ov.w};
    #pragma unroll
    for (int k = 0; k < 4; k++){
        int hw = hw4 + k;
        int a  = lvlbase + hw;
        float px = (float)(hw % W) * st, py = (float)(hw / W) * st;
        float cx = c0a[k]*st + px, cy = c1a[k]*st + py;
        float w = expf(c2a[k])*st,  h = expf(c3a[k])*st;
        float4 o;
        o.x = cx - w*0.5f; o.y = cy - h*0.5f; o.z = cx + w*0.5f; o.w = cy + h*0.5f;
        *reinterpret_cast<float4*>(&g_boxes[((size_t)b*NA + a)*4]) = o;
        float e = expf(-ova[k]);
        g_qobj[(size_t)b*NA + a] = 1.0f + e;
        g_sobj[(size_t)b*NA + a] = 1.0f/(1.0f + e);
    }
}

// ---------------- kernel 2: selection + NMS ----------------
__global__ __launch_bounds__(NTH, 5) void k_nms(
    const float* __restrict__ cls0, const float* __restrict__ cls1,
    const float* __restrict__ cls2){

    extern __shared__ char smraw[];
    unsigned* sc = (unsigned*)smraw;                                      // NA surrogate bits
    unsigned long long* key = (unsigned long long*)(smraw + (size_t)NA*4);// CAP keys

    __shared__ float kx1[KMAX], ky1[KMAX], kx2[KMAX], ky2[KMAX], ksc[KMAX], kar[KMAX];
    __shared__ unsigned hist[256];
    __shared__ int supv[32];
    __shared__ unsigned s_pref; __shared__ int s_kkv; __shared__ int s_total;
    __shared__ int s_cnt, s_kept, s_rank;

    int tid = threadIdx.x;
    int lane = tid & 31, w = tid >> 5;
    int bc  = blockIdx.x;
    int b = bc / NC, c = bc % NC;

    const float* sobj = g_sobj + (size_t)b*NA;
    const float* c0 = cls0 + ((size_t)b*NC + c)*NA0;
    const float* c1 = cls1 + ((size_t)b*NC + c)*NA1;
    const float* c2 = cls2 + ((size_t)b*NC + c)*NA2;

    // ---- bulk surrogate: qs = qapprox(cls) * qobj  (no MUFU; monotone in exact q)
    {
        const float4* c0v = (const float4*)c0;
        const float4* c1v = (const float4*)c1;
        const float4* c2v = (const float4*)c2;
        const float4* q0v = (const float4*)(g_qobj + (size_t)b*NA);
        const float4* q1v = (const float4*)(g_qobj + (size_t)b*NA + NA0);
        const float4* q2v = (const float4*)(g_qobj + (size_t)b*NA + NA0 + NA1);
        uint4* scv = (uint4*)sc;
        for (int i = tid; i < NA0/4; i += NTH){
            float4 cv = c0v[i]; float4 qv = q0v[i]; uint4 o;
            o.x = __float_as_uint(qapprox(cv.x)*qv.x);
            o.y = __float_as_uint(qapprox(cv.y)*qv.y);
            o.z = __float_as_uint(qapprox(cv.z)*qv.z);
            o.w = __float_as_uint(qapprox(cv.w)*qv.w);
            scv[i] = o;
        }
        for (int i = tid; i < NA1/4; i += NTH){
            float4 cv = c1v[i]; float4 qv = q1v[i]; uint4 o;
            o.x = __float_as_uint(qapprox(cv.x)*qv.x);
            o.y = __float_as_uint(qapprox(cv.y)*qv.y);
            o.z = __float_as_uint(qapprox(cv.z)*qv.z);
            o.w = __float_as_uint(qapprox(cv.w)*qv.w);
            scv[NA0/4 + i] = o;
        }
        for (int i = tid; i < NA2/4; i += NTH){
            float4 cv = c2v[i]; float4 qv = q2v[i]; uint4 o;
            o.x = __float_as_uint(qapprox(cv.x)*qv.x);
            o.y = __float_as_uint(qapprox(cv.y)*qv.y);
            o.z = __float_as_uint(qapprox(cv.z)*qv.z);
            o.w = __float_as_uint(qapprox(cv.w)*qv.w);
            scv[(NA0+NA1)/4 + i] = o;
        }
    }
    if (tid == 0){ s_kept = 0; s_rank = 0; }
    __syncthreads();

    const unsigned QHI = __float_as_uint(110.0f);  // over-inclusive score>0.01 band (exact rescore filters)
    unsigned prevT = 0;
    bool done = false;

    while (!done){
        // ---- pass 1 histogram (top byte) + total count
        hist[tid] = 0; __syncthreads();
        for (int a = tid; a < NA; a += NTH){
            unsigned v = sc[a];
            if (v < QHI && v > prevT) atomicAdd(&hist[v>>24], 1u);
        }
        __syncthreads();
        if (tid < 32){
            unsigned cc[8]; unsigned sum = 0;
            #pragma unroll
            for (int j = 0; j < 8; j++){ cc[j] = hist[tid*8+j]; sum += cc[j]; }
            unsigned incl = sum;
            #pragma unroll
            for (int off = 1; off < 32; off <<= 1){
                unsigned n = __shfl_up_sync(FULLM, incl, off);
                if (lane >= off) incl += n;
            }
            unsigned excl = incl - sum;
            unsigned total = __shfl_sync(FULLM, incl, 31);
            if (lane == 0) s_total = (int)total;
            if (total > CAP){
                int kk = BSEL;
                if ((int)excl < kk && kk <= (int)incl){
                    unsigned run = excl;
                    #pragma unroll
                    for (int j = 0; j < 8; j++){
                        if (run + cc[j] >= (unsigned)kk){
                            s_pref = ((unsigned)(tid*8+j)) << 24;
                            s_kkv  = kk - (int)run;
                            break;
                        }
                        run += cc[j];
                    }
                }
            }
        }
        __syncthreads();
        int total = s_total;
        if (total == 0) break;
        bool takeall = (total <= CAP);
        unsigned T = 0xFFFFFFFFu;

        if (!takeall){
            for (int shift = 16; shift >= 0; shift -= 8){
                unsigned prefix = s_pref; int kk = s_kkv;
                unsigned mask = 0xFFFFFFFFu << (shift+8);
                hist[tid] = 0; __syncthreads();
                for (int a = tid; a < NA; a += NTH){
                    unsigned v = sc[a];
                    if (v < QHI && v > prevT && (v & mask) == prefix)
                        atomicAdd(&hist[(v>>shift)&255], 1u);
                }
                __syncthreads();
                if (tid < 32){
                    unsigned cc[8]; unsigned sum = 0;
                    #pragma unroll
                    for (int j = 0; j < 8; j++){ cc[j] = hist[tid*8+j]; sum += cc[j]; }
                    unsigned incl = sum;
                    #pragma unroll
                    for (int off = 1; off < 32; off <<= 1){
                        unsigned n = __shfl_up_sync(FULLM, incl, off);
                        if (lane >= off) incl += n;
                    }
                    unsigned excl = incl - sum;
                    if ((int)excl < kk && kk <= (int)incl){
                        unsigned run = excl;
                        #pragma unroll
                        for (int j = 0; j < 8; j++){
                            if (run + cc[j] >= (unsigned)kk){
                                s_pref = prefix | (((unsigned)(tid*8+j)) << shift);
                                s_kkv  = kk - (int)run;
                                break;
                            }
                            run += cc[j];
                        }
                    }
                }
                __syncthreads();
            }
            T = s_pref;
        }

        // ---- compact candidate indices
        if (tid == 0) s_cnt = 0;
        __syncthreads();
        for (int a = tid; a < NA; a += NTH){
            unsigned v = sc[a];
            if (v < QHI && v > prevT && (takeall || v <= T)){
                int p = atomicAdd(&s_cnt, 1);
                if (p < CAP) key[p] = (unsigned long long)(unsigned)a;
            }
        }
        __syncthreads();
        int cnt = min(s_cnt, CAP);

        // ---- recompute EXACT reference score for selected; build sort keys
        for (int p = tid; p < CAP; p += NTH){
            if (p < cnt){
                int a = (int)(unsigned)key[p];
                float cv;
                if (a < NA0) cv = c0[a];
                else if (a < NA0+NA1) cv = c1[a-NA0];
                else cv = c2[a-NA0-NA1];
                float sg = 1.0f/(1.0f+expf(-cv));     // exact sigmoid(cls)
                float s  = sg * sobj[a];              // exact reference score
                if (s > SCORE_THR)
                    key[p] = ((unsigned long long)(~__float_as_uint(s)) << 32) | (unsigned)a;
                else
                    key[p] = PADKEY;
            } else key[p] = PADKEY;
        }
        __syncthreads();

        // ---- bitonic sort ascending: score desc, ties lower index first
        for (int ksz = 2; ksz <= CAP; ksz <<= 1){
            for (int j = ksz >> 1; j > 0; j >>= 1){
                for (int idx = tid; idx < CAP; idx += NTH){
                    int l = idx ^ j;
                    if (l > idx){
                        unsigned long long a0 = key[idx], a1 = key[l];
                        bool up = ((idx & ksz) == 0);
                        if ((a0 > a1) == up){ key[idx] = a1; key[l] = a0; }
                    }
                }
                __syncthreads();
            }
        }

        // ---- greedy NMS: warp-parallel chunks of 32 candidates
        if (tid < 32) supv[tid] = 0;
        __syncthreads();
        int t0 = 0;
        while (t0 < cnt){
            int K = s_kept, rank = s_rank;
            if (K >= KMAX || rank >= PRE_TOPK) break;
            int chunk_n = min(32, min(cnt - t0, PRE_TOPK - rank));

            bool lv = lane < chunk_n;
            unsigned long long kk64 = lv ? key[t0+lane] : PADKEY;
            bool cvalid = lv && (kk64 != PADKEY);
            float x1=0,y1=0,x2=0,y2=0,ar=0,sval=0;
            if (cvalid){
                int a = (int)(unsigned)(kk64 & 0xFFFFFFFFull);
                sval = __uint_as_float(~(unsigned)(kk64>>32));
                const float4 bb = *reinterpret_cast<const float4*>(&g_boxes[((size_t)b*NA + a)*4]);
                x1=bb.x; y1=bb.y; x2=bb.z; y2=bb.w;
                ar = (x2-x1)*(y2-y1);
            }
            // all 8 warps split the kept-box IoU check
            bool sup = false;
            if (cvalid){
                for (int m = w; m < K; m += 8)
                    sup |= iou_sup(kx1[m],ky1[m],kx2[m],ky2[m],kar[m], x1,y1,x2,y2,ar);
            }
            if (sup) supv[lane] = 1;
            __syncthreads();

            if (w == 0){
                unsigned validmask = __ballot_sync(FULLM, cvalid);
                unsigned conflict = 0;   // lower lanes that would suppress me
                for (int j = 0; j < 31; j++){
                    float X1 = __shfl_sync(FULLM, x1, j);
                    float Y1 = __shfl_sync(FULLM, y1, j);
                    float X2 = __shfl_sync(FULLM, x2, j);
                    float Y2 = __shfl_sync(FULLM, y2, j);
                    float AR = __shfl_sync(FULLM, ar, j);
                    if (cvalid && j < lane && ((validmask>>j)&1u)){
                        if (iou_sup(X1,Y1,X2,Y2,AR, x1,y1,x2,y2,ar)) conflict |= 1u<<j;
                    }
                }
                bool base_ok = cvalid && (supv[lane] == 0);
                unsigned undecided = __ballot_sync(FULLM, base_ok);
                unsigned kept_mask = 0;
                while (undecided){
                    bool und = (undecided >> lane) & 1u;
                    bool decidable = und && ((conflict & undecided) == 0);
                    bool keepme = decidable && ((conflict & kept_mask) == 0);
                    unsigned dec = __ballot_sync(FULLM, decidable);
                    unsigned kp  = __ballot_sync(FULLM, keepme);
                    kept_mask |= kp;
                    undecided &= ~dec;
                }
                int pos = K + __popc(kept_mask & ((1u<<lane)-1u));
                if (((kept_mask>>lane)&1u) && pos < KMAX){
                    kx1[pos]=x1; ky1[pos]=y1; kx2[pos]=x2; ky2[pos]=y2;
                    kar[pos]=ar; ksc[pos]=sval;
                }
                if (lane == 0){
                    s_kept = min(K + __popc(kept_mask), KMAX);
                    s_rank = rank + chunk_n;
                }
                supv[lane] = 0;
            }
            __syncthreads();
            t0 += 32;
        }
        if (s_kept >= KMAX || s_rank >= PRE_TOPK || takeall) done = true;
        else prevT = T;
        __syncthreads();
    }

    // ---- per-class outputs
    int kept = s_kept;
    float* keptS = g_kept_score + (size_t)bc*KMAX;
    float* keptB = g_kept_box   + (size_t)bc*KMAX*4;
    for (int j = tid; j < KMAX; j += NTH){
        if (j < kept){
            keptS[j] = ksc[j];
            keptB[j*4+0]=kx1[j]; keptB[j*4+1]=ky1[j];
            keptB[j*4+2]=kx2[j]; keptB[j*4+3]=ky2[j];
        } else {
            keptS[j] = -1.f;
            keptB[j*4+0]=0.f; keptB[j*4+1]=0.f; keptB[j*4+2]=0.f; keptB[j*4+3]=0.f;
        }
    }
}

// ---------------- kernel 3: per-image global top-100 ----------------
__global__ __launch_bounds__(NTH) void k_final(float* __restrict__ out){
    __shared__ unsigned mapped[TOTK];
    __shared__ unsigned long long key[FSORT];
    __shared__ unsigned hist[256];
    __shared__ unsigned suf[257];
    __shared__ unsigned s_pref; __shared__ int s_kkv;
    __shared__ int s_cnt;

    int tid = threadIdx.x, b = blockIdx.x;
    const float* ks = g_kept_score + (size_t)b*TOTK;
    for (int j = tid; j < TOTK; j += NTH){
        unsigned u = __float_as_uint(ks[j]);
        mapped[j] = (u & 0x80000000u) ? ~u : (u | 0x80000000u);
    }
    __syncthreads();

    unsigned prefix = 0; int kk = KMAX;
    for (int shift = 24; shift >= 0; shift -= 8){
        hist[tid] = 0; __syncthreads();
        unsigned mask = (shift == 24) ? 0u : (0xFFFFFFFFu << (shift+8));
        for (int j = tid; j < TOTK; j += NTH){
            unsigned v = mapped[j];
            if ((v & mask) == prefix) atomicAdd(&hist[(v>>shift)&255], 1u);
        }
        __syncthreads();
        suf[tid] = hist[tid]; if (tid == 0) suf[256] = 0;
        __syncthreads();
        for (int st = 1; st < 256; st <<= 1){
            unsigned add = (tid + st < 256) ? suf[tid+st] : 0u;
            __syncthreads();
            suf[tid] += add;
            __syncthreads();
        }
        if (suf[tid] >= (unsigned)kk && suf[tid+1] < (unsigned)kk){
            s_pref = prefix | ((unsigned)tid << shift);
            s_kkv  = kk - (int)suf[tid+1];
        }
        __syncthreads();
        prefix = s_pref; kk = s_kkv;
        __syncthreads();
    }
    unsigned T = prefix;
    const unsigned MAP0 = 0x80000000u;

    if (tid == 0) s_cnt = 0;
    __syncthreads();
    for (int j = tid; j < TOTK; j += NTH){
        unsigned v = mapped[j];
        if (v >= T && v > MAP0){
            int p = atomicAdd(&s_cnt, 1);
            if (p < FSORT)
                key[p] = ((unsigned long long)v << 32) | (0xFFFFFFFFu - (unsigned)j);
        }
    }
    __syncthreads();
    int cnt = min(s_cnt, FSORT);
    for (int p = cnt + tid; p < FSORT; p += NTH) key[p] = 0ull;
    __syncthreads();

    for (int ksz = 2; ksz <= FSORT; ksz <<= 1){
        for (int j = ksz >> 1; j > 0; j >>= 1){
            if (tid < FSORT){
                int idx = tid, l = idx ^ j;
                if (l > idx){
                    unsigned long long a0 = key[idx], a1 = key[l];
                    bool up = ((idx & ksz) == 0);
                    if ((a0 > a1) == up){ key[idx] = a1; key[l] = a0; }
                }
            }
            __syncthreads();
        }
    }

    float* out_num = out;
    float* out_box = out + BATCH;
    float* out_sc  = out + BATCH + (size_t)BATCH*KMAX*4;
    float* out_cl  = out + BATCH + (size_t)BATCH*KMAX*4 + (size_t)BATCH*KMAX;

    for (int k = tid; k < KMAX; k += NTH){
        bool valid = (k < cnt);
        float s = 0.f, cl = -1.f, b0=0.f, b1=0.f, b2=0.f, b3=0.f;
        if (valid){
            unsigned long long k2 = key[FSORT-1-k];
            int flat = (int)(0xFFFFFFFFu - (unsigned)(k2 & 0xFFFFFFFFull));
            s  = g_kept_score[(size_t)b*TOTK + flat];
            cl = (float)(flat / KMAX);
            const float* bb = &g_kept_box[((size_t)b*TOTK + flat)*4];
            b0 = bb[0]; b1 = bb[1]; b2 = bb[2]; b3 = bb[3];
        }
        out_sc[(size_t)b*KMAX + k] = s;
        out_cl[(size_t)b*KMAX + k] = cl;
        float* ob = &out_box[((size_t)b*KMAX + k)*4];
        ob[0]=b0; ob[1]=b1; ob[2]=b2; ob[3]=b3;
    }
    if (tid == 0) out_num[b] = (float)min(cnt, KMAX);
}

// ---------------- launch ----------------
extern "C" void kernel_launch(void* const* d_in, const int* in_sizes, int n_in,
                              void* d_out, int out_size){
    const float* cls0 = (const float*)d_in[0];
    const float* bb0  = (const float*)d_in[1];
    const float* obj0 = (const float*)d_in[2];
    const float* cls1 = (const float*)d_in[3];
    const float* bb1  = (const float*)d_in[4];
    const float* obj1 = (const float*)d_in[5];
    const float* cls2 = (const float*)d_in[6];
    const float* bb2  = (const float*)d_in[7];
    const float* obj2 = (const float*)d_in[8];
    float* out = (float*)d_out;

    int nthr = BATCH*(NA0+NA1+NA2)/4;
    k_decode<<<(nthr+255)/256, 256>>>(bb0, bb1, bb2, obj0, obj1, obj2);

    size_t smem = (size_t)NA*4 + (size_t)CAP*8;   // 37,696 B
    k_nms<<<BATCH*NC, NTH, smem>>>(cls0, cls1, cls2);

    k_final<<<BATCH, NTH>>>(out);
}